// round 11
// baseline (speedup 1.0000x reference)
#include <cuda_runtime.h>
#include <math.h>

#define HID   1024
#define BSZ   16
#define NOPT  4
#define ROWS  (BSZ*NOPT)    // 64
#define TRUN  2
#define SEQ   1536
#define PLEN  512
#define QLEN  128

#define KSPLIT 32
#define KCHUNK (HID/KSPLIT)   // 32
#define NTILE  64

// Scratch (device globals — no allocation allowed)
__device__ float g_feats[ROWS*HID];
__device__ float g_h1[ROWS*HID];
__device__ float g_h2[ROWS*HID];

// ---------------------------------------------------------------------------
// f32x2 helpers (Blackwell packed fp32 pipe; PTX-only)
// ---------------------------------------------------------------------------
__device__ __forceinline__ unsigned long long bcast_f32x2(float v) {
    unsigned long long r;
    asm("mov.b64 %0, {%1, %1};" : "=l"(r) : "r"(__float_as_uint(v)));
    return r;
}
__device__ __forceinline__ void fma_f32x2(unsigned long long& acc,
                                          unsigned long long a,
                                          unsigned long long b) {
    asm("fma.rn.f32x2 %0, %1, %2, %0;" : "+l"(acc) : "l"(a), "l"(b));
}
__device__ __forceinline__ float lo_f(unsigned long long v) {
    return __uint_as_float((unsigned)(v & 0xFFFFFFFFull));
}
__device__ __forceinline__ float hi_f(unsigned long long v) {
    return __uint_as_float((unsigned)(v >> 32));
}

__device__ __forceinline__ long long opt_at(const void* p, bool is64, int i) {
    if (is64) return ((const long long*)p)[i];
    return (long long)((const int*)p)[i];
}

// ---------------------------------------------------------------------------
// 1) prep (R4 layout, 320 CTAs): blocks [0,256) bias-init h1/h2;
//    blocks [256,320) feats rows. Zeroes the loss output slot.
// ---------------------------------------------------------------------------
__global__ void __launch_bounds__(256)
prep_kernel(const float* __restrict__ emb, const void* __restrict__ opt_length,
            const float* __restrict__ b1, const float* __restrict__ b2,
            float* __restrict__ out, int out_size) {
    if (blockIdx.x == 0 && threadIdx.x == 0) {
        if (out_size == 1)             out[0] = 0.f;
        else if (out_size >= ROWS + 1) out[ROWS] = 0.f;
    }

    if (blockIdx.x < 256) {
        int i = blockIdx.x * 256 + threadIdx.x;     // 0..65535
        int j = i & (HID - 1);
        g_h1[i] = b1[j];
        g_h2[i] = b2[j];
        return;
    }
    int row = blockIdx.x - 256;      // b*NOPT + o
    int b = row >> 2, o = row & 3;

    bool is64 = (((const int*)opt_length)[1] == 0);
    long long cs = 0;
    for (int i = 0; i <= o; i++) cs += opt_at(opt_length, is64, i);
    int ohead = PLEN + QLEN + (int)cs;
    int otail = ohead + (int)opt_at(opt_length, is64, o + 1) - 1;
    int pos[6] = {0, PLEN - 1, PLEN, PLEN + QLEN - 1, ohead, otail};

    int h4 = threadIdx.x * 4;
    float4 acc = make_float4(0.f, 0.f, 0.f, 0.f);
    #pragma unroll
    for (int t = 0; t < TRUN; t++) {
        const float* base = emb + (size_t)(t * BSZ + b) * SEQ * HID;
        #pragma unroll
        for (int p = 0; p < 6; p++) {
            float4 v = *(const float4*)(base + (size_t)pos[p] * HID + h4);
            acc.x += v.x; acc.y += v.y; acc.z += v.z; acc.w += v.w;
        }
    }
    const float s = 0.25f;
    *(float4*)(g_feats + (size_t)row * HID + h4) =
        make_float4(acc.x * s, acc.y * s, acc.z * s, acc.w * s);
}

// ---------------------------------------------------------------------------
// 2) Split-K GEMM — EXACT R4 version (the 21.9us config):
//    out += A(64xK) @ W(KxN), 64x64 tile, K-chunk 32, grid (16,32)=512 CTAs,
//    256 threads, 4x4 micro via FFMA2, red.global.add.v4 epilogue onto
//    bias-initialized out.
// ---------------------------------------------------------------------------
template <int LAYER>
__global__ void __launch_bounds__(256, 6)
gemm_kernel(const float* __restrict__ W) {
    __shared__ float As[KCHUNK][68];   // [k][row], pitch 68
    __shared__ float Ws[KCHUNK][64];   // [k][col]

    const float* A  = (LAYER == 0) ? g_feats : g_h1;
    float*      out = (LAYER == 0) ? g_h1    : g_h2;

    const int n0  = blockIdx.x * NTILE;
    const int k0  = blockIdx.y * KCHUNK;
    const int tid = threadIdx.x;

    {
        int kk4 = (tid & 7) * 4;
        int r   = tid >> 3;
        #pragma unroll
        for (int rr = 0; rr < 2; rr++) {
            int row = r + rr * 32;
            float4 v = *(const float4*)(A + (size_t)row * HID + k0 + kk4);
            if (LAYER == 1) {
                v.x = fmaxf(v.x, 0.f); v.y = fmaxf(v.y, 0.f);
                v.z = fmaxf(v.z, 0.f); v.w = fmaxf(v.w, 0.f);
            }
            As[kk4 + 0][row] = v.x;
            As[kk4 + 1][row] = v.y;
            As[kk4 + 2][row] = v.z;
            As[kk4 + 3][row] = v.w;
        }
    }
    {
        int c4 = (tid & 15) * 4;
        int kk = tid >> 4;
        #pragma unroll
        for (int i = 0; i < 2; i++) {
            int k = kk + i * 16;
            *(float4*)&Ws[k][c4] =
                *(const float4*)(W + (size_t)(k0 + k) * HID + n0 + c4);
        }
    }
    __syncthreads();

    const int c0 = (tid & 15) * 4;
    const int r0 = (tid >> 4) * 4;

    unsigned long long accP[4][2] = {};
    #pragma unroll
    for (int kk = 0; kk < KCHUNK; kk++) {
        ulonglong2 ap = *(const ulonglong2*)&As[kk][r0];
        float4 w = *(const float4*)&Ws[kk][c0];
        unsigned long long w0 = bcast_f32x2(w.x);
        unsigned long long w1 = bcast_f32x2(w.y);
        unsigned long long w2 = bcast_f32x2(w.z);
        unsigned long long w3 = bcast_f32x2(w.w);
        fma_f32x2(accP[0][0], ap.x, w0); fma_f32x2(accP[0][1], ap.y, w0);
        fma_f32x2(accP[1][0], ap.x, w1); fma_f32x2(accP[1][1], ap.y, w1);
        fma_f32x2(accP[2][0], ap.x, w2); fma_f32x2(accP[2][1], ap.y, w2);
        fma_f32x2(accP[3][0], ap.x, w3); fma_f32x2(accP[3][1], ap.y, w3);
    }

    #pragma unroll
    for (int i = 0; i < 4; i++) {
        int h = i >> 1;
        float v0 = (i & 1) ? hi_f(accP[0][h]) : lo_f(accP[0][h]);
        float v1 = (i & 1) ? hi_f(accP[1][h]) : lo_f(accP[1][h]);
        float v2 = (i & 1) ? hi_f(accP[2][h]) : lo_f(accP[2][h]);
        float v3 = (i & 1) ? hi_f(accP[3][h]) : lo_f(accP[3][h]);
        float* p = out + (size_t)(r0 + i) * HID + n0 + c0;
        asm volatile("red.global.add.v4.f32 [%0], {%1, %2, %3, %4};"
                     :: "l"(p), "f"(v0), "f"(v1), "f"(v2), "f"(v3) : "memory");
    }
}

// ---------------------------------------------------------------------------
// 3) gemv+loss, batch-per-CTA, 1024 threads, NO cross-CTA sync.
//    CTA b: 256 lanes per option row; logits + batch-local softmax;
//    loss contribution red.added into the prep-zeroed slot.
// ---------------------------------------------------------------------------
__global__ void __launch_bounds__(1024)
gemv_loss_kernel(const float* __restrict__ W3, const int* __restrict__ y,
                 float* __restrict__ out, int out_size) {
    __shared__ float red[32];    // one slot per warp
    __shared__ float lsh[NOPT];

    const int b    = blockIdx.x;        // batch 0..15
    const int tid  = threadIdx.x;
    const int o    = tid >> 8;          // option 0..3
    const int lane = tid & 255;         // 0..255 within row

    const float* h = g_h2 + (size_t)(b * NOPT + o) * HID;
    float4 hv = *(const float4*)(h + lane * 4);
    float4 wv = *(const float4*)(W3 + lane * 4);
    float s = fmaxf(hv.x, 0.f) * wv.x + fmaxf(hv.y, 0.f) * wv.y
            + fmaxf(hv.z, 0.f) * wv.z + fmaxf(hv.w, 0.f) * wv.w;

    #pragma unroll
    for (int off = 16; off; off >>= 1)
        s += __shfl_down_sync(0xFFFFFFFFu, s, off);
    if ((tid & 31) == 0) red[tid >> 5] = s;
    __syncthreads();

    if (tid < NOPT) {                   // thread o sums its row's 8 warps
        float t = 0.f;
        #pragma unroll
        for (int i = 0; i < 8; i++) t += red[tid * 8 + i];
        lsh[tid] = t;
        if (out_size >= ROWS) out[b * NOPT + tid] = t;
    }
    __syncthreads();

    if (tid == 0) {
        float l0 = lsh[0], l1 = lsh[1], l2 = lsh[2], l3 = lsh[3];
        float m  = fmaxf(fmaxf(l0, l1), fmaxf(l2, l3));
        float se = expf(l0 - m) + expf(l1 - m) + expf(l2 - m) + expf(l3 - m);
        float lse = m + logf(se);
        int yy = y[b];
        float ly = (yy == 0) ? l0 : (yy == 1) ? l1 : (yy == 2) ? l2 : l3;
        float contrib = -(ly - lse) * (1.0f / (float)BSZ);

        float* dst = (out_size == 1) ? out
                   : (out_size >= ROWS + 1) ? (out + ROWS) : nullptr;
        if (dst)
            asm volatile("red.global.add.f32 [%0], %1;"
                         :: "l"(dst), "f"(contrib) : "memory");
    }
}

// ---------------------------------------------------------------------------
// Launch — 4 kernels
// inputs: 0=embeddings 1=W1 2=b1 3=W2 4=b2 5=W3 6=y 7=opt_length
// ---------------------------------------------------------------------------
extern "C" void kernel_launch(void* const* d_in, const int* in_sizes, int n_in,
                              void* d_out, int out_size) {
    const float* emb = (const float*)d_in[0];
    const float* W1  = (const float*)d_in[1];
    const float* b1  = (const float*)d_in[2];
    const float* W2  = (const float*)d_in[3];
    const float* b2  = (const float*)d_in[4];
    const float* W3  = (const float*)d_in[5];
    const int*   y   = (const int*)d_in[6];
    const void*  opt = (const void*)d_in[7];
    float* out = (float*)d_out;

    prep_kernel<<<320, 256>>>(emb, opt, b1, b2, out, out_size);
    gemm_kernel<0><<<dim3(16, KSPLIT), 256>>>(W1);
    gemm_kernel<1><<<dim3(16, KSPLIT), 256>>>(W2);
    gemv_loss_kernel<<<BSZ, 1024>>>(W3, y, out, out_size);
}

// round 12
// speedup vs baseline: 1.3667x; 1.3667x over previous
#include <cuda_runtime.h>
#include <math.h>

#define HID   1024
#define BSZ   16
#define NOPT  4
#define ROWS  (BSZ*NOPT)    // 64
#define TRUN  2
#define SEQ   1536
#define PLEN  512
#define QLEN  128

#define KSPLIT 32
#define KCHUNK (HID/KSPLIT)   // 32
#define NTILE  64

// Scratch (device globals — no allocation allowed)
__device__ float g_feats[ROWS*HID];
__device__ float g_h1[ROWS*HID];
__device__ float g_h2[ROWS*HID];

// ---------------------------------------------------------------------------
// f32x2 helpers
// ---------------------------------------------------------------------------
__device__ __forceinline__ void fma_f32x2(unsigned long long& acc,
                                          unsigned long long a,
                                          unsigned long long b) {
    asm("fma.rn.f32x2 %0, %1, %2, %0;" : "+l"(acc) : "l"(a), "l"(b));
}
__device__ __forceinline__ float lo_f(unsigned long long v) {
    return __uint_as_float((unsigned)(v & 0xFFFFFFFFull));
}
__device__ __forceinline__ float hi_f(unsigned long long v) {
    return __uint_as_float((unsigned)(v >> 32));
}

__device__ __forceinline__ long long opt_at(const void* p, bool is64, int i) {
    if (is64) return ((const long long*)p)[i];
    return (long long)((const int*)p)[i];
}

// ---------------------------------------------------------------------------
// 1) prep (320 CTAs): blocks [0,256) bias-init h1/h2; blocks [256,320) feats.
//    Zeroes the loss output slot.
// ---------------------------------------------------------------------------
__global__ void __launch_bounds__(256)
prep_kernel(const float* __restrict__ emb, const void* __restrict__ opt_length,
            const float* __restrict__ b1, const float* __restrict__ b2,
            float* __restrict__ out, int out_size) {
    if (blockIdx.x == 0 && threadIdx.x == 0) {
        if (out_size == 1)             out[0] = 0.f;
        else if (out_size >= ROWS + 1) out[ROWS] = 0.f;
    }

    if (blockIdx.x < 256) {
        int i = blockIdx.x * 256 + threadIdx.x;     // 0..65535
        int j = i & (HID - 1);
        g_h1[i] = b1[j];
        g_h2[i] = b2[j];
        return;
    }
    int row = blockIdx.x - 256;      // b*NOPT + o
    int b = row >> 2, o = row & 3;

    bool is64 = (((const int*)opt_length)[1] == 0);
    long long cs = 0;
    for (int i = 0; i <= o; i++) cs += opt_at(opt_length, is64, i);
    int ohead = PLEN + QLEN + (int)cs;
    int otail = ohead + (int)opt_at(opt_length, is64, o + 1) - 1;
    int pos[6] = {0, PLEN - 1, PLEN, PLEN + QLEN - 1, ohead, otail};

    int h4 = threadIdx.x * 4;
    float4 acc = make_float4(0.f, 0.f, 0.f, 0.f);
    #pragma unroll
    for (int t = 0; t < TRUN; t++) {
        const float* base = emb + (size_t)(t * BSZ + b) * SEQ * HID;
        #pragma unroll
        for (int p = 0; p < 6; p++) {
            float4 v = *(const float4*)(base + (size_t)pos[p] * HID + h4);
            acc.x += v.x; acc.y += v.y; acc.z += v.z; acc.w += v.w;
        }
    }
    const float s = 0.25f;
    *(float4*)(g_feats + (size_t)row * HID + h4) =
        make_float4(acc.x * s, acc.y * s, acc.z * s, acc.w * s);
}

// ---------------------------------------------------------------------------
// 2) Split-K GEMM, R4 geometry (64x64 tile, K-chunk 32, grid (16,32)=512 CTA,
//    256 thr, 4x4 micro) with duplicated-A smem so the inner loop has ZERO
//    packing movs: per k = 2x LDS.128 (4 dup A rows) + 1x LDS.128 (2 packed
//    W col-pairs) + 8 FFMA2. Epilogue red.global.add.v4 (no in-loop unpack).
// ---------------------------------------------------------------------------
template <int LAYER>
__global__ void __launch_bounds__(256, 4)
gemm_kernel(const float* __restrict__ W) {
    __shared__ float2 As2[KCHUNK][66];   // [k][row] duplicated (a,a), pad 2
    __shared__ float  Ws[KCHUNK][64];    // [k][col] (col pairs pre-packed)

    const float* A  = (LAYER == 0) ? g_feats : g_h1;
    float*      out = (LAYER == 0) ? g_h1    : g_h2;

    const int n0  = blockIdx.x * NTILE;
    const int k0  = blockIdx.y * KCHUNK;
    const int tid = threadIdx.x;

    // Load A tile 64 rows x 32 k (float4 over k), store duplicated-transposed.
    {
        int kk4 = (tid & 7) * 4;      // 0..28
        int r   = tid >> 3;           // 0..31
        #pragma unroll
        for (int rr = 0; rr < 2; rr++) {
            int row = r + rr * 32;
            float4 v = *(const float4*)(A + (size_t)row * HID + k0 + kk4);
            if (LAYER == 1) {
                v.x = fmaxf(v.x, 0.f); v.y = fmaxf(v.y, 0.f);
                v.z = fmaxf(v.z, 0.f); v.w = fmaxf(v.w, 0.f);
            }
            As2[kk4 + 0][row] = make_float2(v.x, v.x);
            As2[kk4 + 1][row] = make_float2(v.y, v.y);
            As2[kk4 + 2][row] = make_float2(v.z, v.z);
            As2[kk4 + 3][row] = make_float2(v.w, v.w);
        }
    }
    // Load W tile 32 k x 64 n, float4 over n.
    {
        int c4 = (tid & 15) * 4;
        int kk = tid >> 4;
        #pragma unroll
        for (int i = 0; i < 2; i++) {
            int k = kk + i * 16;
            *(float4*)&Ws[k][c4] =
                *(const float4*)(W + (size_t)(k0 + k) * HID + n0 + c4);
        }
    }
    __syncthreads();

    const int c0 = (tid & 15) * 4;
    const int r0 = (tid >> 4) * 4;

    // acc[row][colpair]: 4 rows x 2 packed col-pairs (= 4 cols)
    unsigned long long acc[4][2] = {};
    #pragma unroll
    for (int kk = 0; kk < KCHUNK; kk++) {
        ulonglong2 wq = *(const ulonglong2*)&Ws[kk][c0];      // cols c0..c0+3
        ulonglong2 a01 = *(const ulonglong2*)&As2[kk][r0 + 0]; // rows r0,r0+1 dup
        ulonglong2 a23 = *(const ulonglong2*)&As2[kk][r0 + 2]; // rows r0+2,r0+3

        fma_f32x2(acc[0][0], a01.x, wq.x); fma_f32x2(acc[0][1], a01.x, wq.y);
        fma_f32x2(acc[1][0], a01.y, wq.x); fma_f32x2(acc[1][1], a01.y, wq.y);
        fma_f32x2(acc[2][0], a23.x, wq.x); fma_f32x2(acc[2][1], a23.x, wq.y);
        fma_f32x2(acc[3][0], a23.y, wq.x); fma_f32x2(acc[3][1], a23.y, wq.y);
    }

    #pragma unroll
    for (int i = 0; i < 4; i++) {
        float* p = out + (size_t)(r0 + i) * HID + n0 + c0;
        asm volatile("red.global.add.v4.f32 [%0], {%1, %2, %3, %4};"
                     :: "l"(p),
                        "f"(lo_f(acc[i][0])), "f"(hi_f(acc[i][0])),
                        "f"(lo_f(acc[i][1])), "f"(hi_f(acc[i][1])) : "memory");
    }
}

// ---------------------------------------------------------------------------
// 3) gemv+loss, batch-per-CTA (16 CTAs x 256 thr), NO cross-CTA sync:
//    CTA b computes its 4 logits and red.adds its loss part/16 into the
//    prep-zeroed slot (R10 version — measured 5.7us).
// ---------------------------------------------------------------------------
__global__ void __launch_bounds__(256)
gemv_loss_kernel(const float* __restrict__ W3, const int* __restrict__ y,
                 float* __restrict__ out, int out_size) {
    __shared__ float red[8];
    __shared__ float lsh[NOPT];

    const int b    = blockIdx.x;        // batch 0..15
    const int tid  = threadIdx.x;
    const int o    = tid >> 6;          // option 0..3
    const int lane = tid & 63;

    const float* h = g_h2 + (size_t)(b * NOPT + o) * HID;
    float s = 0.f;
    #pragma unroll
    for (int i = 0; i < 4; i++) {       // 64 lanes * 4 iters * float4 = 1024
        int k = (lane + i * 64) * 4;
        float4 hv = *(const float4*)(h + k);
        float4 wv = *(const float4*)(W3 + k);
        s += fmaxf(hv.x, 0.f) * wv.x + fmaxf(hv.y, 0.f) * wv.y
           + fmaxf(hv.z, 0.f) * wv.z + fmaxf(hv.w, 0.f) * wv.w;
    }
    #pragma unroll
    for (int off = 16; off; off >>= 1)
        s += __shfl_down_sync(0xFFFFFFFFu, s, off);
    if ((tid & 31) == 0) red[tid >> 5] = s;
    __syncthreads();

    if (tid < NOPT) lsh[tid] = red[2 * tid] + red[2 * tid + 1];
    __syncthreads();

    if (tid == 0) {
        float l0 = lsh[0], l1 = lsh[1], l2 = lsh[2], l3 = lsh[3];
        if (out_size >= ROWS) {
            out[b * NOPT + 0] = l0; out[b * NOPT + 1] = l1;
            out[b * NOPT + 2] = l2; out[b * NOPT + 3] = l3;
        }
        float m  = fmaxf(fmaxf(l0, l1), fmaxf(l2, l3));
        float se = expf(l0 - m) + expf(l1 - m) + expf(l2 - m) + expf(l3 - m);
        float lse = m + logf(se);
        int yy = y[b];
        float ly = (yy == 0) ? l0 : (yy == 1) ? l1 : (yy == 2) ? l2 : l3;
        float contrib = -(ly - lse) * (1.0f / (float)BSZ);

        float* dst = (out_size == 1) ? out
                   : (out_size >= ROWS + 1) ? (out + ROWS) : nullptr;
        if (dst)
            asm volatile("red.global.add.f32 [%0], %1;"
                         :: "l"(dst), "f"(contrib) : "memory");
    }
}

// ---------------------------------------------------------------------------
// Launch — 4 kernels
// inputs: 0=embeddings 1=W1 2=b1 3=W2 4=b2 5=W3 6=y 7=opt_length
// ---------------------------------------------------------------------------
extern "C" void kernel_launch(void* const* d_in, const int* in_sizes, int n_in,
                              void* d_out, int out_size) {
    const float* emb = (const float*)d_in[0];
    const float* W1  = (const float*)d_in[1];
    const float* b1  = (const float*)d_in[2];
    const float* W2  = (const float*)d_in[3];
    const float* b2  = (const float*)d_in[4];
    const float* W3  = (const float*)d_in[5];
    const int*   y   = (const int*)d_in[6];
    const void*  opt = (const void*)d_in[7];
    float* out = (float*)d_out;

    prep_kernel<<<320, 256>>>(emb, opt, b1, b2, out, out_size);
    gemm_kernel<0><<<dim3(16, KSPLIT), 256>>>(W1);
    gemm_kernel<1><<<dim3(16, KSPLIT), 256>>>(W2);
    gemv_loss_kernel<<<BSZ, 256>>>(W3, y, out, out_size);
}